// round 14
// baseline (speedup 1.0000x reference)
#include <cuda_runtime.h>
#include <cuda_fp16.h>
#include <cstdint>

#define STATE_DIM 512
#define AFEAT 64
#define HID 256
#define HID2 128
#define KACT 1000
#define NROWS 256000
#define TILE_M 64
#define NTILES 4000            // 256000 / 64

__device__ float g_hstate[256 * HID];

__device__ __forceinline__ uint32_t pk(float lo, float hi) {
    __half2 h = __floats2half2_rn(lo, hi);      // low 16 bits = lo
    return *(uint32_t*)&h;
}
__device__ __forceinline__ uint32_t pkr(float lo, float hi) {
    return pk(fmaxf(lo, 0.f), fmaxf(hi, 0.f));
}

// m16n8k16 f16 MMA, f32 accum, C += A*B (row.col)
__device__ __forceinline__ void mma16(float* c, const uint4& a, uint32_t b0, uint32_t b1) {
    asm volatile("mma.sync.aligned.m16n8k16.row.col.f32.f16.f16.f32 "
        "{%0,%1,%2,%3}, {%4,%5,%6,%7}, {%8,%9}, {%0,%1,%2,%3};"
        : "+f"(c[0]), "+f"(c[1]), "+f"(c[2]), "+f"(c[3])
        : "r"(a.x), "r"(a.y), "r"(a.z), "r"(a.w), "r"(b0), "r"(b1));
}

// ---------------------------------------------------------------------------
// hstate: 128 blocks = 32 row-groups (8 rows) x 4 col-groups (64 cols).
// W1 traffic amortized x8 (16 MB total, ~2 us). k ascending -> bit-identical.
// ---------------------------------------------------------------------------
__global__ __launch_bounds__(256) void hstate_kernel(
    const float* __restrict__ state,
    const float* __restrict__ W1,
    const float* __restrict__ b1)
{
    __shared__ float s[8 * STATE_DIM];         // 16 KB
    const int bg = blockIdx.x >> 2;            // 8-row batch group
    const int cg = blockIdx.x & 3;             // 64-col group
    const int t = threadIdx.x;

    for (int i = t * 4; i < 8 * STATE_DIM; i += 1024)
        *(float4*)&s[i] = *(const float4*)&state[bg * 8 * STATE_DIM + i];
    __syncthreads();

    const int col = cg * 64 + (t & 63);
    const int rq = t >> 6;                     // rows rq*2, rq*2+1
    float a0 = b1[col], a1 = a0;
    const float* s0 = s + (rq * 2) * STATE_DIM;
#pragma unroll 8
    for (int k = 0; k < STATE_DIM; k++) {
        float wv = W1[k * HID + col];
        a0 = fmaf(s0[k], wv, a0);
        a1 = fmaf(s0[STATE_DIM + k], wv, a1);
    }
    const int r = bg * 8 + rq * 2;
    g_hstate[r * HID + col]       = a0;
    g_hstate[(r + 1) * HID + col] = a1;
}

// ---------------------------------------------------------------------------
// Main fused MLP. 512 threads = 16 warps, 4(M)x4(N), m=16/warp, TILE_M=64.
// MERGED phase: L2(tile-G) and L1(tile) MMAs interleaved in one loop
// (volatile asm preserves order -> guaranteed pipe mixing), ONE barrier/iter.
// Double-buffered sAfq / h1f / sHS / sOutP.
//
// B-frag uint4: x=(n8=0,k0..7) y=(n8=0,k8..15) z=(n8=1,k0..7) w=(n8=1,k8..15)
// A-frag uint4: x=(r,k0..) y=(r+8,k0..) z=(r,k8..) w=(r+8,k8..), f16x2 lo=even k
//
// SMEM (float units):
//  sW2f 16384 | sW1f 8192 | sB2 128 | sW3 128 | sAf 2x2048 | h1f 2x8192 |
//  sHS 2x512 | sOutP 2x256   -> 46848 floats = 183 KB
// ---------------------------------------------------------------------------
#define OFF_W2F 0
#define OFF_W1F 16384
#define OFF_B2  24576
#define OFF_W3  24704
#define OFF_AF  24832
#define OFF_H1F 28928
#define OFF_HS  45312
#define OFF_OUT 46336
#define SMEM_FLOATS 46848
#define SMEM_BYTES (SMEM_FLOATS * 4)

__global__ void __launch_bounds__(512, 1) actor_main(
    const float* __restrict__ af, const float* __restrict__ W1,
    const float* __restrict__ W2, const float* __restrict__ b2,
    const float* __restrict__ W3, const float* __restrict__ b3,
    float* __restrict__ out)
{
    extern __shared__ float sm[];
    uint32_t* sW2f = (uint32_t*)(sm + OFF_W2F);
    uint32_t* sW1f = (uint32_t*)(sm + OFF_W1F);
    float* sB2   = sm + OFF_B2;
    float* sW3   = sm + OFF_W3;
    uint4* sAfq  = (uint4*)(sm + OFF_AF);      // [2][512]
    float* sHS   = sm + OFF_HS;                // [2][512]
    float* sOutP = sm + OFF_OUT;               // [2][64*4]

    const int t = threadIdx.x;
    const int lane = t & 31;
    const int w = t >> 5;
    const int mg = w & 3;          // m16 slot: rows mg*16 .. +15
    const int ng = w >> 2;         // L1: cols ng*64..; L2: cols ng*32..

    // ---- build W2 frags: [ng(4)][ks(16)][np(2)][lane(32)] uint4 ----
    for (int i = t; i < 16384; i += 512) {
        int ws = i & 3, ln = (i >> 2) & 31;
        int np = (i >> 7) & 1, ks = (i >> 8) & 15, gg = (i >> 12) & 3;
        int krow = ks * 16 + (ws & 1) * 8 + (ln & 3) * 2;
        int col  = gg * 32 + np * 16 + (ws >> 1) * 8 + (ln >> 2);
        sW2f[i] = pk(W2[krow * HID2 + col], W2[(krow + 1) * HID2 + col]);
    }
    // ---- build W1a frags: [ng(4)][ks(4)][np(4)][lane(32)] uint4 ----
    for (int i = t; i < 8192; i += 512) {
        int ws = i & 3, ln = (i >> 2) & 31;
        int np = (i >> 7) & 3, ks = (i >> 9) & 3, gg = (i >> 11) & 3;
        int krow = STATE_DIM + ks * 16 + (ws & 1) * 8 + (ln & 3) * 2;
        int col  = gg * 64 + np * 16 + (ws >> 1) * 8 + (ln >> 2);
        sW1f[i] = pk(W1[krow * HID + col], W1[(krow + 1) * HID + col]);
    }
    if (t < 128) { sB2[t] = b2[t]; sW3[t] = W3[t]; }

    // ---- af staging: thread t owns A-frag slot t = (m16(4), ks(4), lane) ----
    const int s_m16 = t >> 7;
    const int s_ks  = (t >> 5) & 3;
    const int s_row = s_m16 * 16 + (lane >> 2);
    const int s_col = s_ks * 16 + (lane & 3) * 2;

    auto load_af = [&](int tl, uint32_t* pp) {
        const float* base = af + (size_t)(tl * TILE_M + s_row) * AFEAT + s_col;
        float2 v0 = *(const float2*)(base);
        float2 v1 = *(const float2*)(base + 8 * AFEAT);
        float2 v2 = *(const float2*)(base + 8);
        float2 v3 = *(const float2*)(base + 8 * AFEAT + 8);
        pp[0] = pk(v0.x, v0.y);   // (r,   k0)
        pp[1] = pk(v1.x, v1.y);   // (r+8, k0)
        pp[2] = pk(v2.x, v2.y);   // (r,   k0+8)
        pp[3] = pk(v3.x, v3.y);   // (r+8, k0+8)
    };
    auto load_hs = [&](int tl) {
        int r0 = tl * TILE_M;
        int blo = r0 / KACT;
        int bhi = (r0 + TILE_M - 1) / KACT;
        return g_hstate[(t < 256 ? blo : bhi) * HID + (t & 255)];
    };

    const int G = gridDim.x;
    int tile = blockIdx.x;

    // ---- prologue: stage first tile into buffer 0 ----
    {
        uint32_t pp[4];
        load_af(tile, pp);
        sAfq[t] = make_uint4(pp[0], pp[1], pp[2], pp[3]);
        sHS[t] = load_hs(tile);
    }
    __syncthreads();

    const float bias3 = __ldg(b3);
    const uint4* w1v = (const uint4*)sW1f;
    const uint4* w2v = (const uint4*)sW2f;

    int it = 0;
    for (;; it++, tile += G) {
        const int p = it & 1;

        // ---- out(tile-2G): L3 results written at it-1 into sOutP[p^1] ----
        if (it >= 2 && t < 64) {
            float4 v = *(float4*)(sOutP + (p ^ 1) * 256 + t * 4);
            out[(tile - 2 * G) * TILE_M + t] = v.x + v.y + v.z + v.w + bias3;
        }
        if (tile - G >= NTILES) break;

        const bool doL1 = (tile < NTILES);
        const bool doStage = (tile + G < NTILES);
        const bool doL2 = (it >= 1);

        // ---- staging loads for tile+G (packed immediately; STS at end) ----
        uint32_t pp[4]; float hsv = 0.f;
        if (doStage) { load_af(tile + G, pp); hsv = load_hs(tile + G); }

        // ---- init L1 acc from h_state (exact fp32), L2 acc zero ----
        float acc[8][4];
        if (doL1) {
            const float2* hsc2 = (const float2*)(sHS + p * 512);
            const int split = (tile * TILE_M / KACT + 1) * KACT - tile * TILE_M;
            const int r = mg * 16 + (lane >> 2);
            const int selA = (r >= split) ? 128 : 0;
            const int selB = (r + 8 >= split) ? 128 : 0;
            const int c2base = (ng * 64 + 2 * (lane & 3)) >> 1;
#pragma unroll
            for (int nt = 0; nt < 8; nt++) {
                float2 va = hsc2[selA + c2base + nt * 4];
                float2 vb = hsc2[selB + c2base + nt * 4];
                acc[nt][0] = va.x; acc[nt][1] = va.y;
                acc[nt][2] = vb.x; acc[nt][3] = vb.y;
            }
        }
        float acc2[4][4];
#pragma unroll
        for (int nt = 0; nt < 4; nt++)
#pragma unroll
        for (int rg = 0; rg < 4; rg++) acc2[nt][rg] = 0.f;

        // ---- MERGED MMA loop: L2(tile-G) every k, L1(tile) on k<4 ----
        const uint4* h1prev = (const uint4*)(sm + OFF_H1F + (p ^ 1) * 8192);
#pragma unroll
        for (int k = 0; k < 16; k++) {
            if (doL2) {
                uint4 a  = h1prev[(mg * 16 + k) * 32 + lane];
                uint4 b0 = w2v[((ng * 16 + k) * 2 + 0) * 32 + lane];
                uint4 b1q = w2v[((ng * 16 + k) * 2 + 1) * 32 + lane];
                mma16(acc2[0], a, b0.x, b0.y);
                mma16(acc2[1], a, b0.z, b0.w);
                mma16(acc2[2], a, b1q.x, b1q.y);
                mma16(acc2[3], a, b1q.z, b1q.w);
            }
            if (k < 4 && doL1) {
                uint4 a = sAfq[p * 512 + (mg * 4 + k) * 32 + lane];
#pragma unroll
                for (int np = 0; np < 4; np++) {
                    uint4 b = w1v[((ng * 4 + k) * 4 + np) * 32 + lane];
                    mma16(acc[np * 2],     a, b.x, b.y);
                    mma16(acc[np * 2 + 1], a, b.z, b.w);
                }
            }
        }

        // ---- ep1(tile): relu -> f16 -> h1f[p] as L2 A-frags ----
        if (doL1) {
            uint4* h1cur = (uint4*)(sm + OFF_H1F + p * 8192);
#pragma unroll
            for (int q = 0; q < 4; q++) {
                uint4 v;
                v.x = pkr(acc[2 * q][0],     acc[2 * q][1]);
                v.y = pkr(acc[2 * q][2],     acc[2 * q][3]);
                v.z = pkr(acc[2 * q + 1][0], acc[2 * q + 1][1]);
                v.w = pkr(acc[2 * q + 1][2], acc[2 * q + 1][3]);
                h1cur[(mg * 16 + ng * 4 + q) * 32 + lane] = v;
            }
        }

        // ---- L3(tile-G): relu(C2 + b2) . W3 partials -> sOutP[p] ----
        if (doL2) {
            float part[2] = {0.f, 0.f};
#pragma unroll
            for (int nt = 0; nt < 4; nt++)
#pragma unroll
            for (int rg = 0; rg < 4; rg++) {
                int c = ng * 32 + nt * 8 + 2 * (lane & 3) + (rg & 1);
                float v = fmaxf(acc2[nt][rg] + sB2[c], 0.f);
                part[rg >> 1] += v * sW3[c];
            }
#pragma unroll
            for (int rb = 0; rb < 2; rb++) {
                float v = part[rb];
                v += __shfl_xor_sync(0xffffffffu, v, 1);
                v += __shfl_xor_sync(0xffffffffu, v, 2);
                if ((lane & 3) == 0)
                    sOutP[p * 256 + (mg * 16 + rb * 8 + (lane >> 2)) * 4 + ng] = v;
            }
        }

        // ---- staging stores for tile+G into buffers p^1 ----
        if (doStage) {
            sAfq[(p ^ 1) * 512 + t] = make_uint4(pp[0], pp[1], pp[2], pp[3]);
            sHS[(p ^ 1) * 512 + t] = hsv;
        }
        __syncthreads();   // the only barrier per iteration
    }
}

// ---------------------------------------------------------------------------
extern "C" void kernel_launch(void* const* d_in, const int* in_sizes, int n_in,
                              void* d_out, int out_size)
{
    const float* state = (const float*)d_in[0];
    const float* afeats = (const float*)d_in[1];
    const float* W1    = (const float*)d_in[2];
    const float* b1    = (const float*)d_in[3];
    const float* W2    = (const float*)d_in[4];
    const float* b2    = (const float*)d_in[5];
    const float* W3    = (const float*)d_in[6];
    const float* b3    = (const float*)d_in[7];
    float* out = (float*)d_out;
    (void)in_sizes; (void)n_in; (void)out_size;

    static int sm_count = 0;
    if (sm_count == 0) {
        cudaDeviceGetAttribute(&sm_count, cudaDevAttrMultiProcessorCount, 0);
        if (sm_count <= 0) sm_count = 148;
        cudaFuncSetAttribute(actor_main,
                             cudaFuncAttributeMaxDynamicSharedMemorySize, SMEM_BYTES);
    }

    hstate_kernel<<<128, 256>>>(state, W1, b1);
    actor_main<<<sm_count, 512, SMEM_BYTES>>>(afeats, W1, W2, b2, W3, b3, out);
}

// round 15
// speedup vs baseline: 1.1558x; 1.1558x over previous
#include <cuda_runtime.h>
#include <cuda_fp16.h>
#include <cstdint>

#define STATE_DIM 512
#define AFEAT 64
#define HID 256
#define HID2 128
#define KACT 1000
#define NROWS 256000
#define TILE_M 64
#define NTILES 4000            // 256000 / 64

__device__ float g_hstate[256 * HID];

__device__ __forceinline__ uint32_t pk(float lo, float hi) {
    __half2 h = __floats2half2_rn(lo, hi);      // low 16 bits = lo
    return *(uint32_t*)&h;
}
__device__ __forceinline__ uint32_t pkr(float lo, float hi) {
    return pk(fmaxf(lo, 0.f), fmaxf(hi, 0.f));
}

// m16n8k16 f16 MMA, f32 accum, C += A*B (row.col)
__device__ __forceinline__ void mma16(float* c, const uint4& a, uint32_t b0, uint32_t b1) {
    asm volatile("mma.sync.aligned.m16n8k16.row.col.f32.f16.f16.f32 "
        "{%0,%1,%2,%3}, {%4,%5,%6,%7}, {%8,%9}, {%0,%1,%2,%3};"
        : "+f"(c[0]), "+f"(c[1]), "+f"(c[2]), "+f"(c[3])
        : "r"(a.x), "r"(a.y), "r"(a.z), "r"(a.w), "r"(b0), "r"(b1));
}

#define GBAR(gid) asm volatile("bar.sync %0, 256;" :: "r"((gid) + 1) : "memory")

// ---------------------------------------------------------------------------
// hstate (R14 version — best measured): 128 blocks = 32 row-groups (8 rows)
// x 4 col-groups (64 cols). W1 traffic amortized x8. k ascending.
// ---------------------------------------------------------------------------
__global__ __launch_bounds__(256) void hstate_kernel(
    const float* __restrict__ state,
    const float* __restrict__ W1,
    const float* __restrict__ b1)
{
    __shared__ float s[8 * STATE_DIM];         // 16 KB
    const int bg = blockIdx.x >> 2;            // 8-row batch group
    const int cg = blockIdx.x & 3;             // 64-col group
    const int t = threadIdx.x;

    for (int i = t * 4; i < 8 * STATE_DIM; i += 1024)
        *(float4*)&s[i] = *(const float4*)&state[bg * 8 * STATE_DIM + i];
    __syncthreads();

    const int col = cg * 64 + (t & 63);
    const int rq = t >> 6;                     // rows rq*2, rq*2+1
    float a0 = b1[col], a1 = a0;
    const float* s0 = s + (rq * 2) * STATE_DIM;
#pragma unroll 8
    for (int k = 0; k < STATE_DIM; k++) {
        float wv = W1[k * HID + col];
        a0 = fmaf(s0[k], wv, a0);
        a1 = fmaf(s0[STATE_DIM + k], wv, a1);
    }
    const int r = bg * 8 + rq * 2;
    g_hstate[r * HID + col]       = a0;
    g_hstate[(r + 1) * HID + col] = a1;
}

// ---------------------------------------------------------------------------
// Main fused MLP (R12 version — best measured main, 97.6 us).
// 512 threads = 2 groups x 8 warps, per-group tile streams, named barriers.
//
// SMEM (float units):
//  sW2f 16384 | sW1f 8192 | sB2 128 | sW3 128 |
//  per group (13824): sAf 2x2048 | sH1f 8192 | sHS 2x512 | sOutP 2x256
// ---------------------------------------------------------------------------
#define OFF_W2F 0
#define OFF_W1F 16384
#define OFF_B2  24576
#define OFF_W3  24704
#define OFF_G0  24832
#define GSTRIDE 13824
#define GOFF_AF  0
#define GOFF_H1F 4096
#define GOFF_HS  12288
#define GOFF_OUT 13312
#define SMEM_FLOATS (24832 + 2 * 13824)
#define SMEM_BYTES (SMEM_FLOATS * 4)

__global__ void __launch_bounds__(512, 1) actor_main(
    const float* __restrict__ af, const float* __restrict__ W1,
    const float* __restrict__ W2, const float* __restrict__ b2,
    const float* __restrict__ W3, const float* __restrict__ b3,
    float* __restrict__ out)
{
    extern __shared__ float sm[];
    uint32_t* sW2f = (uint32_t*)(sm + OFF_W2F);
    uint32_t* sW1f = (uint32_t*)(sm + OFF_W1F);
    float* sB2  = sm + OFF_B2;
    float* sW3  = sm + OFF_W3;

    const int t = threadIdx.x;
    const int lane = t & 31;
    const int w = t >> 5;
    const int g = w >> 3;          // group 0/1
    const int wg = w & 7;          // warp in group
    const int mg = wg & 1;         // rows mg*32 .. +31
    const int ng = wg >> 1;        // L1: cols ng*64..; L2: cols ng*32..
    const int tg = t & 255;        // thread in group

    float* GB = sm + OFF_G0 + g * GSTRIDE;
    uint4*    sAfq  = (uint4*)(GB + GOFF_AF);     // [2][512] uint4
    uint32_t* sH1f  = (uint32_t*)(GB + GOFF_H1F); // 2048 uint4
    float*    sHS   = GB + GOFF_HS;               // [2][512]
    float*    sOutP = GB + GOFF_OUT;              // [2][64*4]

    // ---- build W2 frags: [ng(4)][ks(16)][np(2)][lane(32)] uint4 ----
    for (int i = t; i < 16384; i += 512) {
        int ws = i & 3, ln = (i >> 2) & 31;
        int np = (i >> 7) & 1, ks = (i >> 8) & 15, gg = (i >> 12) & 3;
        int krow = ks * 16 + (ws & 1) * 8 + (ln & 3) * 2;
        int col  = gg * 32 + np * 16 + (ws >> 1) * 8 + (ln >> 2);
        sW2f[i] = pk(W2[krow * HID2 + col], W2[(krow + 1) * HID2 + col]);
    }
    // ---- build W1a frags: [ng(4)][ks(4)][np(4)][lane(32)] uint4 ----
    for (int i = t; i < 8192; i += 512) {
        int ws = i & 3, ln = (i >> 2) & 31;
        int np = (i >> 7) & 3, ks = (i >> 9) & 3, gg = (i >> 11) & 3;
        int krow = STATE_DIM + ks * 16 + (ws & 1) * 8 + (ln & 3) * 2;
        int col  = gg * 64 + np * 16 + (ws >> 1) * 8 + (ln >> 2);
        sW1f[i] = pk(W1[krow * HID + col], W1[(krow + 1) * HID + col]);
    }
    if (t < 128) { sB2[t] = b2[t]; sW3[t] = W3[t]; }

    // ---- af staging: each group thread fills 2 A-frag uint4 per tile ----
    const int s_rowoff = (lane >> 2);
    const int s_coloff = (lane & 3) * 2;

    auto load_af = [&](int tl, uint32_t* pp) {
#pragma unroll
        for (int j = 0; j < 2; j++) {
            int idx = tg + j * 256;
            int rg16 = idx >> 7, ks = (idx >> 5) & 3;
            const float* base = af + (size_t)(tl * TILE_M + rg16 * 16 + s_rowoff) * AFEAT
                                   + ks * 16 + s_coloff;
            float2 v0 = *(const float2*)(base);
            float2 v1 = *(const float2*)(base + 8 * AFEAT);
            float2 v2 = *(const float2*)(base + 8);
            float2 v3 = *(const float2*)(base + 8 * AFEAT + 8);
            pp[j * 4 + 0] = pk(v0.x, v0.y);
            pp[j * 4 + 1] = pk(v1.x, v1.y);
            pp[j * 4 + 2] = pk(v2.x, v2.y);
            pp[j * 4 + 3] = pk(v3.x, v3.y);
        }
    };
    auto store_af = [&](const uint32_t* pp, int buf) {
#pragma unroll
        for (int j = 0; j < 2; j++)
            sAfq[buf * 512 + tg + j * 256] =
                make_uint4(pp[j * 4 + 0], pp[j * 4 + 1], pp[j * 4 + 2], pp[j * 4 + 3]);
    };
    auto stage_hs = [&](int tl, int buf) {
        int r0 = tl * TILE_M;
        int blo = r0 / KACT;
        int bhi = (r0 + TILE_M - 1) / KACT;
        sHS[buf * 512 + tg]       = g_hstate[blo * HID + tg];
        sHS[buf * 512 + 256 + tg] = g_hstate[bhi * HID + tg];
    };

    __syncthreads();               // weights ready (both groups)

    const int G = gridDim.x;
    const int tstep = 2 * G;
    int tile = blockIdx.x * 2 + g;

    // ---- prologue: stage first tile for this group ----
    {
        uint32_t pp[8];
        load_af(tile, pp);
        store_af(pp, 0);
        stage_hs(tile, 0);
    }
    GBAR(g);

    const float bias3 = __ldg(b3);
    const uint4* w1v = (const uint4*)sW1f;
    const uint4* w2v = (const uint4*)sW2f;
    const uint4* h1v = (const uint4*)sH1f;

    int it = 0;
    for (; tile < NTILES; tile += tstep, it++) {
        const int row0 = tile * TILE_M;
        const int ntile = tile + tstep;
        const int cur = it & 1, nxt = cur ^ 1;
        const int split = (row0 / KACT + 1) * KACT - row0;

        // ---- write out(tile - tstep): reduce ng-slots from sOutP[nxt] ----
        if (it >= 1 && tg < 64) {
            float4 v = *(float4*)(sOutP + nxt * 256 + tg * 4);
            out[row0 - tstep * TILE_M + tg] = v.x + v.y + v.z + v.w + bias3;
        }

        // ---- prefetch next tile's af ----
        uint32_t pp[8];
        if (ntile < NTILES) load_af(ntile, pp);

        // ---- L1: C = af @ W1a, init C = h_state (exact fp32) ----
        // C-frag: bit0 = col parity, bit1 = row+8
        float acc[2][8][4];
        const float* hsc = sHS + cur * 512;
#pragma unroll
        for (int mf = 0; mf < 2; mf++) {
            const int r = mg * 32 + mf * 16 + (lane >> 2);
#pragma unroll
            for (int nt = 0; nt < 8; nt++)
#pragma unroll
            for (int rg = 0; rg < 4; rg++) {
                int rr = r + (rg >> 1) * 8;
                int c = ng * 64 + nt * 8 + 2 * (lane & 3) + (rg & 1);
                acc[mf][nt][rg] = hsc[(rr >= split ? 256 : 0) + c];
            }
        }
#pragma unroll
        for (int ks = 0; ks < 4; ks++) {
            uint4 a0 = sAfq[cur * 512 + ((mg * 2 + 0) * 4 + ks) * 32 + lane];
            uint4 a1 = sAfq[cur * 512 + ((mg * 2 + 1) * 4 + ks) * 32 + lane];
#pragma unroll
            for (int np = 0; np < 4; np++) {
                uint4 b = w1v[((ng * 4 + ks) * 4 + np) * 32 + lane];
                mma16(acc[0][np * 2],     a0, b.x, b.y);
                mma16(acc[0][np * 2 + 1], a0, b.z, b.w);
                mma16(acc[1][np * 2],     a1, b.x, b.y);
                mma16(acc[1][np * 2 + 1], a1, b.z, b.w);
            }
        }
        // ---- ep1: relu -> f16 pairs -> sH1f as L2 A-frags ----
#pragma unroll
        for (int mf = 0; mf < 2; mf++)
#pragma unroll
        for (int q = 0; q < 4; q++) {
            uint4 v;
            v.x = pkr(acc[mf][2 * q][0],     acc[mf][2 * q][1]);
            v.y = pkr(acc[mf][2 * q][2],     acc[mf][2 * q][3]);
            v.z = pkr(acc[mf][2 * q + 1][0], acc[mf][2 * q + 1][1]);
            v.w = pkr(acc[mf][2 * q + 1][2], acc[mf][2 * q + 1][3]);
            ((uint4*)sH1f)[((mg * 2 + mf) * 16 + ng * 4 + q) * 32 + lane] = v;
        }
        GBAR(g);   // S1: h1 ready, prev-buffer reads all done

        // ---- stage next tile while L2 runs ----
        if (ntile < NTILES) {
            store_af(pp, nxt);
            stage_hs(ntile, nxt);
        }

        // ---- L2: C2 = h1 @ W2 ----
        float acc2[2][4][4];
#pragma unroll
        for (int mf = 0; mf < 2; mf++)
#pragma unroll
        for (int nt = 0; nt < 4; nt++)
#pragma unroll
        for (int rg = 0; rg < 4; rg++) acc2[mf][nt][rg] = 0.f;
#pragma unroll
        for (int ks = 0; ks < 16; ks++) {
            uint4 a0 = h1v[((mg * 2 + 0) * 16 + ks) * 32 + lane];
            uint4 a1 = h1v[((mg * 2 + 1) * 16 + ks) * 32 + lane];
#pragma unroll
            for (int np = 0; np < 2; np++) {
                uint4 b = w2v[((ng * 16 + ks) * 2 + np) * 32 + lane];
                mma16(acc2[0][np * 2],     a0, b.x, b.y);
                mma16(acc2[0][np * 2 + 1], a0, b.z, b.w);
                mma16(acc2[1][np * 2],     a1, b.x, b.y);
                mma16(acc2[1][np * 2 + 1], a1, b.z, b.w);
            }
        }

        // ---- L3: relu(C2 + b2) . W3 partials -> sOutP[cur][row][ng] ----
#pragma unroll
        for (int mf = 0; mf < 2; mf++) {
            float part[2] = {0.f, 0.f};
#pragma unroll
            for (int nt = 0; nt < 4; nt++)
#pragma unroll
            for (int rg = 0; rg < 4; rg++) {
                int c = ng * 32 + nt * 8 + 2 * (lane & 3) + (rg & 1);
                float v = fmaxf(acc2[mf][nt][rg] + sB2[c], 0.f);
                part[rg >> 1] += v * sW3[c];
            }
#pragma unroll
            for (int rb = 0; rb < 2; rb++) {
                float v = part[rb];
                v += __shfl_xor_sync(0xffffffffu, v, 1);
                v += __shfl_xor_sync(0xffffffffu, v, 2);
                if ((lane & 3) == 0)
                    sOutP[cur * 256 + (mg * 32 + mf * 16 + rb * 8 + (lane >> 2)) * 4 + ng] = v;
            }
        }
        GBAR(g);   // S2: L3 stores + h1 reads done; buffers flip
    }

    // ---- drain: write the final tile's output ----
    if (it >= 1 && tg < 64) {
        const int last = tile - tstep;
        float4 v = *(float4*)(sOutP + ((it - 1) & 1) * 256 + tg * 4);
        out[last * TILE_M + tg] = v.x + v.y + v.z + v.w + bias3;
    }
}

// ---------------------------------------------------------------------------
extern "C" void kernel_launch(void* const* d_in, const int* in_sizes, int n_in,
                              void* d_out, int out_size)
{
    const float* state = (const float*)d_in[0];
    const float* afeats = (const float*)d_in[1];
    const float* W1    = (const float*)d_in[2];
    const float* b1    = (const float*)d_in[3];
    const float* W2    = (const float*)d_in[4];
    const float* b2    = (const float*)d_in[5];
    const float* W3    = (const float*)d_in[6];
    const float* b3    = (const float*)d_in[7];
    float* out = (float*)d_out;
    (void)in_sizes; (void)n_in; (void)out_size;

    static int sm_count = 0;
    if (sm_count == 0) {
        cudaDeviceGetAttribute(&sm_count, cudaDevAttrMultiProcessorCount, 0);
        if (sm_count <= 0) sm_count = 148;
        cudaFuncSetAttribute(actor_main,
                             cudaFuncAttributeMaxDynamicSharedMemorySize, SMEM_BYTES);
    }

    hstate_kernel<<<128, 256>>>(state, W1, b1);
    actor_main<<<sm_count, 512, SMEM_BYTES>>>(afeats, W1, W2, b2, W3, b3, out);
}

// round 16
// speedup vs baseline: 1.1762x; 1.0177x over previous
#include <cuda_runtime.h>
#include <cuda_fp16.h>
#include <cstdint>

#define STATE_DIM 512
#define AFEAT 64
#define HID 256
#define HID2 128
#define KACT 1000
#define NROWS 256000
#define TILE_M 64
#define NTILES 4000            // 256000 / 64

__device__ float g_hstate[256 * HID];

__device__ __forceinline__ uint32_t pk(float lo, float hi) {
    __half2 h = __floats2half2_rn(lo, hi);      // low 16 bits = lo
    return *(uint32_t*)&h;
}
__device__ __forceinline__ uint32_t pkr(float lo, float hi) {
    return pk(fmaxf(lo, 0.f), fmaxf(hi, 0.f));
}

// m16n8k16 f16 MMA, f32 accum, C += A*B (row.col)
__device__ __forceinline__ void mma16(float* c, const uint4& a, uint32_t b0, uint32_t b1) {
    asm volatile("mma.sync.aligned.m16n8k16.row.col.f32.f16.f16.f32 "
        "{%0,%1,%2,%3}, {%4,%5,%6,%7}, {%8,%9}, {%0,%1,%2,%3};"
        : "+f"(c[0]), "+f"(c[1]), "+f"(c[2]), "+f"(c[3])
        : "r"(a.x), "r"(a.y), "r"(a.z), "r"(a.w), "r"(b0), "r"(b1));
}

#define GBAR(gid) asm volatile("bar.sync %0, 256;" :: "r"((gid) + 1) : "memory")

// ---------------------------------------------------------------------------
// hstate (R14 version — best measured): 128 blocks = 32 row-groups (8 rows)
// x 4 col-groups (64 cols). W1 traffic amortized x8. k ascending.
// ---------------------------------------------------------------------------
__global__ __launch_bounds__(256) void hstate_kernel(
    const float* __restrict__ state,
    const float* __restrict__ W1,
    const float* __restrict__ b1)
{
    __shared__ float s[8 * STATE_DIM];         // 16 KB
    const int bg = blockIdx.x >> 2;            // 8-row batch group
    const int cg = blockIdx.x & 3;             // 64-col group
    const int t = threadIdx.x;

    for (int i = t * 4; i < 8 * STATE_DIM; i += 1024)
        *(float4*)&s[i] = *(const float4*)&state[bg * 8 * STATE_DIM + i];
    __syncthreads();

    const int col = cg * 64 + (t & 63);
    const int rq = t >> 6;                     // rows rq*2, rq*2+1
    float a0 = b1[col], a1 = a0;
    const float* s0 = s + (rq * 2) * STATE_DIM;
#pragma unroll 8
    for (int k = 0; k < STATE_DIM; k++) {
        float wv = W1[k * HID + col];
        a0 = fmaf(s0[k], wv, a0);
        a1 = fmaf(s0[STATE_DIM + k], wv, a1);
    }
    const int r = bg * 8 + rq * 2;
    g_hstate[r * HID + col]       = a0;
    g_hstate[(r + 1) * HID + col] = a1;
}

// ---------------------------------------------------------------------------
// Main fused MLP (R12 structure + R16 LDS-replication cuts).
// 512 threads = 2 groups x 8 warps, per-group tile streams, named barriers.
// New: hs-init fast path (uniform-batch tiles: 8 LDS.64 instead of 64 LDS.32
// per warp) and L3 b2/W3 hoist (8 LDS.64 loaded once, reused across mf).
//
// SMEM (float units):
//  sW2f 16384 | sW1f 8192 | sB2 128 | sW3 128 |
//  per group (13824): sAf 2x2048 | sH1f 8192 | sHS 2x512 | sOutP 2x256
// ---------------------------------------------------------------------------
#define OFF_W2F 0
#define OFF_W1F 16384
#define OFF_B2  24576
#define OFF_W3  24704
#define OFF_G0  24832
#define GSTRIDE 13824
#define GOFF_AF  0
#define GOFF_H1F 4096
#define GOFF_HS  12288
#define GOFF_OUT 13312
#define SMEM_FLOATS (24832 + 2 * 13824)
#define SMEM_BYTES (SMEM_FLOATS * 4)

__global__ void __launch_bounds__(512, 1) actor_main(
    const float* __restrict__ af, const float* __restrict__ W1,
    const float* __restrict__ W2, const float* __restrict__ b2,
    const float* __restrict__ W3, const float* __restrict__ b3,
    float* __restrict__ out)
{
    extern __shared__ float sm[];
    uint32_t* sW2f = (uint32_t*)(sm + OFF_W2F);
    uint32_t* sW1f = (uint32_t*)(sm + OFF_W1F);
    float* sB2  = sm + OFF_B2;
    float* sW3  = sm + OFF_W3;

    const int t = threadIdx.x;
    const int lane = t & 31;
    const int w = t >> 5;
    const int g = w >> 3;          // group 0/1
    const int wg = w & 7;          // warp in group
    const int mg = wg & 1;         // rows mg*32 .. +31
    const int ng = wg >> 1;        // L1: cols ng*64..; L2: cols ng*32..
    const int tg = t & 255;        // thread in group

    float* GB = sm + OFF_G0 + g * GSTRIDE;
    uint4*    sAfq  = (uint4*)(GB + GOFF_AF);     // [2][512] uint4
    uint32_t* sH1f  = (uint32_t*)(GB + GOFF_H1F); // 2048 uint4
    float*    sHS   = GB + GOFF_HS;               // [2][512]
    float*    sOutP = GB + GOFF_OUT;              // [2][64*4]

    // ---- build W2 frags: [ng(4)][ks(16)][np(2)][lane(32)] uint4 ----
    for (int i = t; i < 16384; i += 512) {
        int ws = i & 3, ln = (i >> 2) & 31;
        int np = (i >> 7) & 1, ks = (i >> 8) & 15, gg = (i >> 12) & 3;
        int krow = ks * 16 + (ws & 1) * 8 + (ln & 3) * 2;
        int col  = gg * 32 + np * 16 + (ws >> 1) * 8 + (ln >> 2);
        sW2f[i] = pk(W2[krow * HID2 + col], W2[(krow + 1) * HID2 + col]);
    }
    // ---- build W1a frags: [ng(4)][ks(4)][np(4)][lane(32)] uint4 ----
    for (int i = t; i < 8192; i += 512) {
        int ws = i & 3, ln = (i >> 2) & 31;
        int np = (i >> 7) & 3, ks = (i >> 9) & 3, gg = (i >> 11) & 3;
        int krow = STATE_DIM + ks * 16 + (ws & 1) * 8 + (ln & 3) * 2;
        int col  = gg * 64 + np * 16 + (ws >> 1) * 8 + (ln >> 2);
        sW1f[i] = pk(W1[krow * HID + col], W1[(krow + 1) * HID + col]);
    }
    if (t < 128) { sB2[t] = b2[t]; sW3[t] = W3[t]; }

    // ---- af staging: each group thread fills 2 A-frag uint4 per tile ----
    const int s_rowoff = (lane >> 2);
    const int s_coloff = (lane & 3) * 2;

    auto load_af = [&](int tl, uint32_t* pp) {
#pragma unroll
        for (int j = 0; j < 2; j++) {
            int idx = tg + j * 256;
            int rg16 = idx >> 7, ks = (idx >> 5) & 3;
            const float* base = af + (size_t)(tl * TILE_M + rg16 * 16 + s_rowoff) * AFEAT
                                   + ks * 16 + s_coloff;
            float2 v0 = *(const float2*)(base);
            float2 v1 = *(const float2*)(base + 8 * AFEAT);
            float2 v2 = *(const float2*)(base + 8);
            float2 v3 = *(const float2*)(base + 8 * AFEAT + 8);
            pp[j * 4 + 0] = pk(v0.x, v0.y);
            pp[j * 4 + 1] = pk(v1.x, v1.y);
            pp[j * 4 + 2] = pk(v2.x, v2.y);
            pp[j * 4 + 3] = pk(v3.x, v3.y);
        }
    };
    auto store_af = [&](const uint32_t* pp, int buf) {
#pragma unroll
        for (int j = 0; j < 2; j++)
            sAfq[buf * 512 + tg + j * 256] =
                make_uint4(pp[j * 4 + 0], pp[j * 4 + 1], pp[j * 4 + 2], pp[j * 4 + 3]);
    };
    auto stage_hs = [&](int tl, int buf) {
        int r0 = tl * TILE_M;
        int blo = r0 / KACT;
        int bhi = (r0 + TILE_M - 1) / KACT;
        sHS[buf * 512 + tg]       = g_hstate[blo * HID + tg];
        sHS[buf * 512 + 256 + tg] = g_hstate[bhi * HID + tg];
    };

    __syncthreads();               // weights ready (both groups)

    const int G = gridDim.x;
    const int tstep = 2 * G;
    int tile = blockIdx.x * 2 + g;

    // ---- prologue: stage first tile for this group ----
    {
        uint32_t pp[8];
        load_af(tile, pp);
        store_af(pp, 0);
        stage_hs(tile, 0);
    }
    GBAR(g);

    const float bias3 = __ldg(b3);
    const uint4* w1v = (const uint4*)sW1f;
    const uint4* w2v = (const uint4*)sW2f;
    const uint4* h1v = (const uint4*)sH1f;

    int it = 0;
    for (; tile < NTILES; tile += tstep, it++) {
        const int row0 = tile * TILE_M;
        const int ntile = tile + tstep;
        const int cur = it & 1, nxt = cur ^ 1;
        const int split = (row0 / KACT + 1) * KACT - row0;

        // ---- write out(tile - tstep): reduce ng-slots from sOutP[nxt] ----
        if (it >= 1 && tg < 64) {
            float4 v = *(float4*)(sOutP + nxt * 256 + tg * 4);
            out[row0 - tstep * TILE_M + tg] = v.x + v.y + v.z + v.w + bias3;
        }

        // ---- prefetch next tile's af ----
        uint32_t pp[8];
        if (ntile < NTILES) load_af(ntile, pp);

        // ---- L1: C = af @ W1a, init C = h_state (exact fp32) ----
        // C-frag: bit0 = col parity, bit1 = row+8
        float acc[2][8][4];
        const float* hsc = sHS + cur * 512;
        if (split >= TILE_M) {
            // Fast path (93.6% of tiles): whole tile one batch -> all 4 row
            // variants share one value per col pair. 8 LDS.64 per warp.
            const float2* h2 = (const float2*)hsc;
            const int cb = ng * 32 + (lane & 3);
#pragma unroll
            for (int nt = 0; nt < 8; nt++) {
                float2 v = h2[cb + nt * 4];
                acc[0][nt][0] = v.x; acc[0][nt][1] = v.y;
                acc[0][nt][2] = v.x; acc[0][nt][3] = v.y;
                acc[1][nt][0] = v.x; acc[1][nt][1] = v.y;
                acc[1][nt][2] = v.x; acc[1][nt][3] = v.y;
            }
        } else {
#pragma unroll
            for (int mf = 0; mf < 2; mf++) {
                const int r = mg * 32 + mf * 16 + (lane >> 2);
#pragma unroll
                for (int nt = 0; nt < 8; nt++)
#pragma unroll
                for (int rg = 0; rg < 4; rg++) {
                    int rr = r + (rg >> 1) * 8;
                    int c = ng * 64 + nt * 8 + 2 * (lane & 3) + (rg & 1);
                    acc[mf][nt][rg] = hsc[(rr >= split ? 256 : 0) + c];
                }
            }
        }
#pragma unroll
        for (int ks = 0; ks < 4; ks++) {
            uint4 a0 = sAfq[cur * 512 + ((mg * 2 + 0) * 4 + ks) * 32 + lane];
            uint4 a1 = sAfq[cur * 512 + ((mg * 2 + 1) * 4 + ks) * 32 + lane];
#pragma unroll
            for (int np = 0; np < 4; np++) {
                uint4 b = w1v[((ng * 4 + ks) * 4 + np) * 32 + lane];
                mma16(acc[0][np * 2],     a0, b.x, b.y);
                mma16(acc[0][np * 2 + 1], a0, b.z, b.w);
                mma16(acc[1][np * 2],     a1, b.x, b.y);
                mma16(acc[1][np * 2 + 1], a1, b.z, b.w);
            }
        }
        // ---- ep1: relu -> f16 pairs -> sH1f as L2 A-frags ----
#pragma unroll
        for (int mf = 0; mf < 2; mf++)
#pragma unroll
        for (int q = 0; q < 4; q++) {
            uint4 v;
            v.x = pkr(acc[mf][2 * q][0],     acc[mf][2 * q][1]);
            v.y = pkr(acc[mf][2 * q][2],     acc[mf][2 * q][3]);
            v.z = pkr(acc[mf][2 * q + 1][0], acc[mf][2 * q + 1][1]);
            v.w = pkr(acc[mf][2 * q + 1][2], acc[mf][2 * q + 1][3]);
            ((uint4*)sH1f)[((mg * 2 + mf) * 16 + ng * 4 + q) * 32 + lane] = v;
        }
        GBAR(g);   // S1: h1 ready, prev-buffer reads all done

        // ---- stage next tile while L2 runs ----
        if (ntile < NTILES) {
            store_af(pp, nxt);
            stage_hs(ntile, nxt);
        }

        // ---- L2: C2 = h1 @ W2 ----
        float acc2[2][4][4];
#pragma unroll
        for (int mf = 0; mf < 2; mf++)
#pragma unroll
        for (int nt = 0; nt < 4; nt++)
#pragma unroll
        for (int rg = 0; rg < 4; rg++) acc2[mf][nt][rg] = 0.f;
#pragma unroll
        for (int ks = 0; ks < 16; ks++) {
            uint4 a0 = h1v[((mg * 2 + 0) * 16 + ks) * 32 + lane];
            uint4 a1 = h1v[((mg * 2 + 1) * 16 + ks) * 32 + lane];
#pragma unroll
            for (int np = 0; np < 2; np++) {
                uint4 b = w2v[((ng * 16 + ks) * 2 + np) * 32 + lane];
                mma16(acc2[0][np * 2],     a0, b.x, b.y);
                mma16(acc2[0][np * 2 + 1], a0, b.z, b.w);
                mma16(acc2[1][np * 2],     a1, b.x, b.y);
                mma16(acc2[1][np * 2 + 1], a1, b.z, b.w);
            }
        }

        // ---- L3: relu(C2 + b2) . W3 partials -> sOutP[cur][row][ng] ----
        // b2/W3 operands hoisted: mf-invariant, pair-structured -> 8 LDS.64.
        {
            float2 b2p[4], w3p[4];
            const float2* b2v2 = (const float2*)sB2;
            const float2* w3v2 = (const float2*)sW3;
            const int cb = ng * 16 + (lane & 3);
#pragma unroll
            for (int nt = 0; nt < 4; nt++) {
                b2p[nt] = b2v2[cb + nt * 4];
                w3p[nt] = w3v2[cb + nt * 4];
            }
#pragma unroll
            for (int mf = 0; mf < 2; mf++) {
                float part[2] = {0.f, 0.f};
#pragma unroll
                for (int nt = 0; nt < 4; nt++)
#pragma unroll
                for (int rg = 0; rg < 4; rg++) {
                    float bb = (rg & 1) ? b2p[nt].y : b2p[nt].x;
                    float ww = (rg & 1) ? w3p[nt].y : w3p[nt].x;
                    float v = fmaxf(acc2[mf][nt][rg] + bb, 0.f);
                    part[rg >> 1] += v * ww;
                }
#pragma unroll
                for (int rb = 0; rb < 2; rb++) {
                    float v = part[rb];
                    v += __shfl_xor_sync(0xffffffffu, v, 1);
                    v += __shfl_xor_sync(0xffffffffu, v, 2);
                    if ((lane & 3) == 0)
                        sOutP[cur * 256 + (mg * 32 + mf * 16 + rb * 8 + (lane >> 2)) * 4 + ng] = v;
                }
            }
        }
        GBAR(g);   // S2: L3 stores + h1 reads done; buffers flip
    }

    // ---- drain: write the final tile's output ----
    if (it >= 1 && tg < 64) {
        const int last = tile - tstep;
        float4 v = *(float4*)(sOutP + ((it - 1) & 1) * 256 + tg * 4);
        out[last * TILE_M + tg] = v.x + v.y + v.z + v.w + bias3;
    }
}

// ---------------------------------------------------------------------------
extern "C" void kernel_launch(void* const* d_in, const int* in_sizes, int n_in,
                              void* d_out, int out_size)
{
    const float* state = (const float*)d_in[0];
    const float* afeats = (const float*)d_in[1];
    const float* W1    = (const float*)d_in[2];
    const float* b1    = (const float*)d_in[3];
    const float* W2    = (const float*)d_in[4];
    const float* b2    = (const float*)d_in[5];
    const float* W3    = (const float*)d_in[6];
    const float* b3    = (const float*)d_in[7];
    float* out = (float*)d_out;
    (void)in_sizes; (void)n_in; (void)out_size;

    static int sm_count = 0;
    if (sm_count == 0) {
        cudaDeviceGetAttribute(&sm_count, cudaDevAttrMultiProcessorCount, 0);
        if (sm_count <= 0) sm_count = 148;
        cudaFuncSetAttribute(actor_main,
                             cudaFuncAttributeMaxDynamicSharedMemorySize, SMEM_BYTES);
    }

    hstate_kernel<<<128, 256>>>(state, W1, b1);
    actor_main<<<sm_count, 512, SMEM_BYTES>>>(afeats, W1, W2, b2, W3, b3, out);
}

// round 17
// speedup vs baseline: 1.2031x; 1.0228x over previous
#include <cuda_runtime.h>
#include <cuda_fp16.h>
#include <cstdint>

#define STATE_DIM 512
#define AFEAT 64
#define HID 256
#define HID2 128
#define KACT 1000
#define NROWS 256000
#define TILE_M 64
#define NTILES 4000            // 256000 / 64

__device__ float g_hstate[256 * HID];
__device__ unsigned g_tile_ctr = 0;   // monotonic across launches; per-launch
                                      // advance is EXACTLY NTILES + n_streams

__device__ __forceinline__ uint32_t pk(float lo, float hi) {
    __half2 h = __floats2half2_rn(lo, hi);      // low 16 bits = lo
    return *(uint32_t*)&h;
}
__device__ __forceinline__ uint32_t pkr(float lo, float hi) {
    return pk(fmaxf(lo, 0.f), fmaxf(hi, 0.f));
}

// m16n8k16 f16 MMA, f32 accum, C += A*B (row.col)
__device__ __forceinline__ void mma16(float* c, const uint4& a, uint32_t b0, uint32_t b1) {
    asm volatile("mma.sync.aligned.m16n8k16.row.col.f32.f16.f16.f32 "
        "{%0,%1,%2,%3}, {%4,%5,%6,%7}, {%8,%9}, {%0,%1,%2,%3};"
        : "+f"(c[0]), "+f"(c[1]), "+f"(c[2]), "+f"(c[3])
        : "r"(a.x), "r"(a.y), "r"(a.z), "r"(a.w), "r"(b0), "r"(b1));
}

#define GBAR(gid) asm volatile("bar.sync %0, 256;" :: "r"((gid) + 1) : "memory")

// ---------------------------------------------------------------------------
// hstate (R14 version): 128 blocks = 32 row-groups (8 rows) x 4 col-groups.
// ---------------------------------------------------------------------------
__global__ __launch_bounds__(256) void hstate_kernel(
    const float* __restrict__ state,
    const float* __restrict__ W1,
    const float* __restrict__ b1)
{
    __shared__ float s[8 * STATE_DIM];         // 16 KB
    const int bg = blockIdx.x >> 2;
    const int cg = blockIdx.x & 3;
    const int t = threadIdx.x;

    for (int i = t * 4; i < 8 * STATE_DIM; i += 1024)
        *(float4*)&s[i] = *(const float4*)&state[bg * 8 * STATE_DIM + i];
    __syncthreads();

    const int col = cg * 64 + (t & 63);
    const int rq = t >> 6;
    float a0 = b1[col], a1 = a0;
    const float* s0 = s + (rq * 2) * STATE_DIM;
#pragma unroll 8
    for (int k = 0; k < STATE_DIM; k++) {
        float wv = W1[k * HID + col];
        a0 = fmaf(s0[k], wv, a0);
        a1 = fmaf(s0[STATE_DIM + k], wv, a1);
    }
    const int r = bg * 8 + rq * 2;
    g_hstate[r * HID + col]       = a0;
    g_hstate[(r + 1) * HID + col] = a1;
}

// ---------------------------------------------------------------------------
// Main fused MLP (R16 + dynamic tile scheduler).
// 512 threads = 2 groups x 8 warps; each group is an independent persistent
// stream pulling tiles from a global atomic counter (1-ahead lookahead,
// handed off via parity-buffered SMEM slot across the existing barriers).
//
// SMEM (float units):
//  sW2f 16384 | sW1f 8192 | sB2 128 | sW3 128 |
//  per group (13856): sAf 2x2048 | sH1f 8192 | sHS 2x512 | sOutP 2x256 | sched 4+pad
// ---------------------------------------------------------------------------
#define OFF_W2F 0
#define OFF_W1F 16384
#define OFF_B2  24576
#define OFF_W3  24704
#define OFF_G0  24832
#define GSTRIDE 13856
#define GOFF_AF  0
#define GOFF_H1F 4096
#define GOFF_HS  12288
#define GOFF_OUT 13312
#define GOFF_SCH 13824
#define SMEM_FLOATS (24832 + 2 * 13856)
#define SMEM_BYTES (SMEM_FLOATS * 4)

__global__ void __launch_bounds__(512, 1) actor_main(
    const float* __restrict__ af, const float* __restrict__ W1,
    const float* __restrict__ W2, const float* __restrict__ b2,
    const float* __restrict__ W3, const float* __restrict__ b3,
    float* __restrict__ out)
{
    extern __shared__ float sm[];
    uint32_t* sW2f = (uint32_t*)(sm + OFF_W2F);
    uint32_t* sW1f = (uint32_t*)(sm + OFF_W1F);
    float* sB2  = sm + OFF_B2;
    float* sW3  = sm + OFF_W3;

    const int t = threadIdx.x;
    const int lane = t & 31;
    const int w = t >> 5;
    const int g = w >> 3;          // group 0/1
    const int wg = w & 7;          // warp in group
    const int mg = wg & 1;         // rows mg*32 .. +31
    const int ng = wg >> 1;        // L1: cols ng*64..; L2: cols ng*32..
    const int tg = t & 255;        // thread in group

    float* GB = sm + OFF_G0 + g * GSTRIDE;
    uint4*    sAfq  = (uint4*)(GB + GOFF_AF);     // [2][512] uint4
    uint32_t* sH1f  = (uint32_t*)(GB + GOFF_H1F); // 2048 uint4
    float*    sHS   = GB + GOFF_HS;               // [2][512]
    float*    sOutP = GB + GOFF_OUT;              // [2][64*4]
    int*      sched = (int*)(GB + GOFF_SCH);      // [4]

    const unsigned FSTRIDE = (unsigned)NTILES + 2u * gridDim.x;
    auto fetch_tile = [&]() -> int {              // call from tg==0 only
        unsigned f = atomicAdd(&g_tile_ctr, 1u);
        unsigned gen = f / FSTRIDE;
        int tl = (int)(f - gen * FSTRIDE);
        return (tl < NTILES) ? tl : -1;
    };

    // ---- build W2 frags: [ng(4)][ks(16)][np(2)][lane(32)] uint4 ----
    for (int i = t; i < 16384; i += 512) {
        int ws = i & 3, ln = (i >> 2) & 31;
        int np = (i >> 7) & 1, ks = (i >> 8) & 15, gg = (i >> 12) & 3;
        int krow = ks * 16 + (ws & 1) * 8 + (ln & 3) * 2;
        int col  = gg * 32 + np * 16 + (ws >> 1) * 8 + (ln >> 2);
        sW2f[i] = pk(W2[krow * HID2 + col], W2[(krow + 1) * HID2 + col]);
    }
    // ---- build W1a frags: [ng(4)][ks(4)][np(4)][lane(32)] uint4 ----
    for (int i = t; i < 8192; i += 512) {
        int ws = i & 3, ln = (i >> 2) & 31;
        int np = (i >> 7) & 3, ks = (i >> 9) & 3, gg = (i >> 11) & 3;
        int krow = STATE_DIM + ks * 16 + (ws & 1) * 8 + (ln & 3) * 2;
        int col  = gg * 64 + np * 16 + (ws >> 1) * 8 + (ln >> 2);
        sW1f[i] = pk(W1[krow * HID + col], W1[(krow + 1) * HID + col]);
    }
    if (t < 128) { sB2[t] = b2[t]; sW3[t] = W3[t]; }

    // ---- scheduler prologue: fetch first two tiles for this group ----
    if (tg == 0) {
        sched[0] = fetch_tile();
        sched[1] = fetch_tile();
    }
    __syncthreads();               // weights + sched visible (CTA-wide, once)

    // ---- af staging helpers ----
    const int s_rowoff = (lane >> 2);
    const int s_coloff = (lane & 3) * 2;

    auto load_af = [&](int tl, uint32_t* pp) {
#pragma unroll
        for (int j = 0; j < 2; j++) {
            int idx = tg + j * 256;
            int rg16 = idx >> 7, ks = (idx >> 5) & 3;
            const float* base = af + (size_t)(tl * TILE_M + rg16 * 16 + s_rowoff) * AFEAT
                                   + ks * 16 + s_coloff;
            float2 v0 = *(const float2*)(base);
            float2 v1 = *(const float2*)(base + 8 * AFEAT);
            float2 v2 = *(const float2*)(base + 8);
            float2 v3 = *(const float2*)(base + 8 * AFEAT + 8);
            pp[j * 4 + 0] = pk(v0.x, v0.y);
            pp[j * 4 + 1] = pk(v1.x, v1.y);
            pp[j * 4 + 2] = pk(v2.x, v2.y);
            pp[j * 4 + 3] = pk(v3.x, v3.y);
        }
    };
    auto store_af = [&](const uint32_t* pp, int buf) {
#pragma unroll
        for (int j = 0; j < 2; j++)
            sAfq[buf * 512 + tg + j * 256] =
                make_uint4(pp[j * 4 + 0], pp[j * 4 + 1], pp[j * 4 + 2], pp[j * 4 + 3]);
    };
    auto stage_hs = [&](int tl, int buf) {
        int r0 = tl * TILE_M;
        int blo = r0 / KACT;
        int bhi = (r0 + TILE_M - 1) / KACT;
        sHS[buf * 512 + tg]       = g_hstate[blo * HID + tg];
        sHS[buf * 512 + 256 + tg] = g_hstate[bhi * HID + tg];
    };

    int tile  = sched[0];
    int ntile = sched[1];

    // ---- data prologue: stage first tile into buffer 0 ----
    {
        uint32_t pp[8];
        load_af(tile, pp);
        store_af(pp, 0);
        stage_hs(tile, 0);
    }
    GBAR(g);

    const float bias3 = __ldg(b3);
    const uint4* w1v = (const uint4*)sW1f;
    const uint4* w2v = (const uint4*)sW2f;
    const uint4* h1v = (const uint4*)sH1f;

    int otile = -1;
    int cur = 0;
    while (tile >= 0) {
        const int nxt = cur ^ 1;

        // ---- fetch next-next tile (guarded: never fetch after exhausted) ----
        if (tg == 0)
            sched[2 + cur] = (ntile >= 0) ? fetch_tile() : -1;

        // ---- write out(otile): reduce ng-slots from sOutP[nxt] ----
        if (otile >= 0 && tg < 64) {
            float4 v = *(float4*)(sOutP + nxt * 256 + tg * 4);
            out[otile * TILE_M + tg] = v.x + v.y + v.z + v.w + bias3;
        }

        // ---- prefetch ntile's af ----
        uint32_t pp[8];
        if (ntile >= 0) load_af(ntile, pp);

        // ---- L1: C = af @ W1a, init C = h_state (exact fp32) ----
        // C-frag: bit0 = col parity, bit1 = row+8
        const int row0 = tile * TILE_M;
        const int split = (row0 / KACT + 1) * KACT - row0;
        float acc[2][8][4];
        const float* hsc = sHS + cur * 512;
        if (split >= TILE_M) {
            // Fast path (93.6% of tiles): one batch -> 8 LDS.64 per warp.
            const float2* h2 = (const float2*)hsc;
            const int cb = ng * 32 + (lane & 3);
#pragma unroll
            for (int nt = 0; nt < 8; nt++) {
                float2 v = h2[cb + nt * 4];
                acc[0][nt][0] = v.x; acc[0][nt][1] = v.y;
                acc[0][nt][2] = v.x; acc[0][nt][3] = v.y;
                acc[1][nt][0] = v.x; acc[1][nt][1] = v.y;
                acc[1][nt][2] = v.x; acc[1][nt][3] = v.y;
            }
        } else {
#pragma unroll
            for (int mf = 0; mf < 2; mf++) {
                const int r = mg * 32 + mf * 16 + (lane >> 2);
#pragma unroll
                for (int nt = 0; nt < 8; nt++)
#pragma unroll
                for (int rg = 0; rg < 4; rg++) {
                    int rr = r + (rg >> 1) * 8;
                    int c = ng * 64 + nt * 8 + 2 * (lane & 3) + (rg & 1);
                    acc[mf][nt][rg] = hsc[(rr >= split ? 256 : 0) + c];
                }
            }
        }
#pragma unroll
        for (int ks = 0; ks < 4; ks++) {
            uint4 a0 = sAfq[cur * 512 + ((mg * 2 + 0) * 4 + ks) * 32 + lane];
            uint4 a1 = sAfq[cur * 512 + ((mg * 2 + 1) * 4 + ks) * 32 + lane];
#pragma unroll
            for (int np = 0; np < 4; np++) {
                uint4 b = w1v[((ng * 4 + ks) * 4 + np) * 32 + lane];
                mma16(acc[0][np * 2],     a0, b.x, b.y);
                mma16(acc[0][np * 2 + 1], a0, b.z, b.w);
                mma16(acc[1][np * 2],     a1, b.x, b.y);
                mma16(acc[1][np * 2 + 1], a1, b.z, b.w);
            }
        }
        // ---- ep1: relu -> f16 pairs -> sH1f as L2 A-frags ----
#pragma unroll
        for (int mf = 0; mf < 2; mf++)
#pragma unroll
        for (int q = 0; q < 4; q++) {
            uint4 v;
            v.x = pkr(acc[mf][2 * q][0],     acc[mf][2 * q][1]);
            v.y = pkr(acc[mf][2 * q][2],     acc[mf][2 * q][3]);
            v.z = pkr(acc[mf][2 * q + 1][0], acc[mf][2 * q + 1][1]);
            v.w = pkr(acc[mf][2 * q + 1][2], acc[mf][2 * q + 1][3]);
            ((uint4*)sH1f)[((mg * 2 + mf) * 16 + ng * 4 + q) * 32 + lane] = v;
        }
        GBAR(g);   // S1: h1 ready, prev-buffer reads all done

        // ---- stage ntile while L2 runs ----
        if (ntile >= 0) {
            store_af(pp, nxt);
            stage_hs(ntile, nxt);
        }

        // ---- L2: C2 = h1 @ W2 ----
        float acc2[2][4][4];
#pragma unroll
        for (int mf = 0; mf < 2; mf++)
#pragma unroll
        for (int nt = 0; nt < 4; nt++)
#pragma unroll
        for (int rg = 0; rg < 4; rg++) acc2[mf][nt][rg] = 0.f;
#pragma unroll
        for (int ks = 0; ks < 16; ks++) {
            uint4 a0 = h1v[((mg * 2 + 0) * 16 + ks) * 32 + lane];
            uint4 a1 = h1v[((mg * 2 + 1) * 16 + ks) * 32 + lane];
#pragma unroll
            for (int np = 0; np < 2; np++) {
                uint4 b = w2v[((ng * 16 + ks) * 2 + np) * 32 + lane];
                mma16(acc2[0][np * 2],     a0, b.x, b.y);
                mma16(acc2[0][np * 2 + 1], a0, b.z, b.w);
                mma16(acc2[1][np * 2],     a1, b.x, b.y);
                mma16(acc2[1][np * 2 + 1], a1, b.z, b.w);
            }
        }

        // ---- L3: relu(C2 + b2) . W3 partials -> sOutP[cur][row][ng] ----
        {
            float2 b2p[4], w3p[4];
            const float2* b2v2 = (const float2*)sB2;
            const float2* w3v2 = (const float2*)sW3;
            const int cb = ng * 16 + (lane & 3);
#pragma unroll
            for (int nt = 0; nt < 4; nt++) {
                b2p[nt] = b2v2[cb + nt * 4];
                w3p[nt] = w3v2[cb + nt * 4];
            }
#pragma unroll
            for (int mf = 0; mf < 2; mf++) {
                float part[2] = {0.f, 0.f};
#pragma unroll
                for (int nt = 0; nt < 4; nt++)
#pragma unroll
                for (int rg = 0; rg < 4; rg++) {
                    float bb = (rg & 1) ? b2p[nt].y : b2p[nt].x;
                    float ww = (rg & 1) ? w3p[nt].y : w3p[nt].x;
                    float v = fmaxf(acc2[mf][nt][rg] + bb, 0.f);
                    part[rg >> 1] += v * ww;
                }
#pragma unroll
                for (int rb = 0; rb < 2; rb++) {
                    float v = part[rb];
                    v += __shfl_xor_sync(0xffffffffu, v, 1);
                    v += __shfl_xor_sync(0xffffffffu, v, 2);
                    if ((lane & 3) == 0)
                        sOutP[cur * 256 + (mg * 32 + mf * 16 + rb * 8 + (lane >> 2)) * 4 + ng] = v;
                }
            }
        }
        GBAR(g);   // S2: L3 stores + h1 reads + sched write all done

        otile = tile;
        tile  = ntile;
        ntile = sched[2 + cur];
        cur = nxt;
    }

    // ---- drain: write the final tile's output (partials in sOutP[cur^1]) ----
    if (otile >= 0 && tg < 64) {
        float4 v = *(float4*)(sOutP + (cur ^ 1) * 256 + tg * 4);
        out[otile * TILE_M + tg] = v.x + v.y + v.z + v.w + bias3;
    }
}

// ---------------------------------------------------------------------------
extern "C" void kernel_launch(void* const* d_in, const int* in_sizes, int n_in,
                              void* d_out, int out_size)
{
    const float* state = (const float*)d_in[0];
    const float* afeats = (const float*)d_in[1];
    const float* W1    = (const float*)d_in[2];
    const float* b1    = (const float*)d_in[3];
    const float* W2    = (const float*)d_in[4];
    const float* b2    = (const float*)d_in[5];
    const float* W3    = (const float*)d_in[6];
    const float* b3    = (const float*)d_in[7];
    float* out = (float*)d_out;
    (void)in_sizes; (void)n_in; (void)out_size;

    static int sm_count = 0;
    if (sm_count == 0) {
        cudaDeviceGetAttribute(&sm_count, cudaDevAttrMultiProcessorCount, 0);
        if (sm_count <= 0) sm_count = 148;
        cudaFuncSetAttribute(actor_main,
                             cudaFuncAttributeMaxDynamicSharedMemorySize, SMEM_BYTES);
    }

    hstate_kernel<<<128, 256>>>(state, W1, b1);
    actor_main<<<sm_count, 512, SMEM_BYTES>>>(afeats, W1, W2, b2, W3, b3, out);
}